// round 3
// baseline (speedup 1.0000x reference)
#include <cuda_runtime.h>
#include <cstdint>

#define NB 2
#define NS 2048
#define ND 768
#define NH 12
#define NHD 64
#define NFF 3072
#define NM (NB*NS)   // 4096 rows

// ---------------- scratch (static device allocations, allowed) ----------------
__device__ float g_q[NB*NH*NS*NHD];
__device__ float g_k[NB*NH*NS*NHD];
__device__ float g_v[NB*NH*NS*NHD];
__device__ float g_attn[NM*ND];
__device__ float g_tmp[NM*ND];
__device__ float g_x1[NM*ND];
__device__ float g_ff[(size_t)NM*NFF];

// ---------------------------------------------------------------------------
// Tiled SGEMM: C[m,n] = sum_k A[m,k] * W[n,k] + bias[n]  (+relu / +residual)
// 64x64 block tile, 256 threads, 4x4 per thread, K-tile 32.
// headsplit=1 stores C into (B,H,S,HD) layout (n -> h,hd ; m -> b,s).
// ---------------------------------------------------------------------------
__global__ __launch_bounds__(256) void gemm_kernel(
    const float* __restrict__ A, const float* __restrict__ W,
    const float* __restrict__ bias, const float* __restrict__ res,
    float* __restrict__ C, int M, int N, int K, int relu, int headsplit)
{
    __shared__ __align__(16) float As[32][68];
    __shared__ __align__(16) float Bs[32][68];
    const int tid = threadIdx.x;
    const int ty = tid >> 4, tx = tid & 15;
    const int m0 = blockIdx.y << 6, n0 = blockIdx.x << 6;

    float acc[4][4] = {};

    for (int k0 = 0; k0 < K; k0 += 32) {
        #pragma unroll
        for (int c = 0; c < 2; c++) {
            int idx = tid + (c << 8);          // 0..511
            int row = idx >> 3;                 // 0..63
            int col = (idx & 7) << 2;           // 0..28 step 4
            float4 va = *reinterpret_cast<const float4*>(A + (size_t)(m0+row)*K + k0 + col);
            As[col+0][row] = va.x; As[col+1][row] = va.y;
            As[col+2][row] = va.z; As[col+3][row] = va.w;
            float4 vb = *reinterpret_cast<const float4*>(W + (size_t)(n0+row)*K + k0 + col);
            Bs[col+0][row] = vb.x; Bs[col+1][row] = vb.y;
            Bs[col+2][row] = vb.z; Bs[col+3][row] = vb.w;
        }
        __syncthreads();
        #pragma unroll
        for (int kk = 0; kk < 32; kk++) {
            float4 a4 = *reinterpret_cast<const float4*>(&As[kk][ty << 2]);
            float4 b4 = *reinterpret_cast<const float4*>(&Bs[kk][tx << 2]);
            float av[4] = {a4.x, a4.y, a4.z, a4.w};
            float bv[4] = {b4.x, b4.y, b4.z, b4.w};
            #pragma unroll
            for (int i = 0; i < 4; i++)
                #pragma unroll
                for (int j = 0; j < 4; j++)
                    acc[i][j] = fmaf(av[i], bv[j], acc[i][j]);
        }
        __syncthreads();
    }

    #pragma unroll
    for (int i = 0; i < 4; i++) {
        int m = m0 + (ty << 2) + i;
        #pragma unroll
        for (int j = 0; j < 4; j++) {
            int n = n0 + (tx << 2) + j;
            float v = acc[i][j] + bias[n];
            if (relu) v = fmaxf(v, 0.0f);
            if (res)  v += res[(size_t)m * N + n];
            if (headsplit) {
                int h = n >> 6, hd = n & 63;
                int b = m >> 11, s = m & (NS - 1);
                C[(((size_t)(b * NH + h)) * NS + s) * NHD + hd] = v;
            } else {
                C[(size_t)m * N + n] = v;
            }
        }
    }
}

// ---------------------------------------------------------------------------
// Flash attention, fp32. 64 queries x 64-key tiles, 256 threads, 4x4/thread.
// ALiBi + causal mask computed analytically. P tile reuses the K smem buffer.
// Q/K stored transposed [d][row] in smem; V natural [row][d].
// ---------------------------------------------------------------------------
__global__ __launch_bounds__(256) void attn_kernel(
    const float* __restrict__ Q, const float* __restrict__ K,
    const float* __restrict__ V, float* __restrict__ O)
{
    extern __shared__ __align__(16) float sm[];
    float* Qs = sm;                 // [64][68]  (transposed: [d][q])
    float* Ks = sm + 64 * 68;       // [64][68]  (transposed: [d][k]), reused as P[k][q]
    float* Vs = sm + 2 * 64 * 68;   // [64][68]  (natural:   [k][d])

    const int tid = threadIdx.x;
    const int ty = tid >> 4, tx = tid & 15;
    const int q0 = blockIdx.x << 6;
    const int bh = blockIdx.y;
    const int h  = bh % NH;
    const int b  = bh / NH;
    const size_t base = (size_t)bh * NS * NHD;
    const float slope = exp2f(-(8.0f / NH) * (float)(h + 1));

    // load Q tile transposed
    #pragma unroll
    for (int c = 0; c < 4; c++) {
        int idx = tid + (c << 8);     // 0..1023
        int row = idx >> 4;           // 0..63
        int col = (idx & 15) << 2;    // 0..60 step 4
        float4 v = *reinterpret_cast<const float4*>(Q + base + (size_t)(q0 + row) * NHD + col);
        Qs[(col + 0) * 68 + row] = v.x; Qs[(col + 1) * 68 + row] = v.y;
        Qs[(col + 2) * 68 + row] = v.z; Qs[(col + 3) * 68 + row] = v.w;
    }

    float m_r[4], l_r[4];
    float acc_o[4][4] = {};
    #pragma unroll
    for (int i = 0; i < 4; i++) { m_r[i] = -1e30f; l_r[i] = 0.0f; }

    const int nt = (q0 >> 6) + 1;   // causal: key tiles 0..q0/64
    for (int t = 0; t < nt; t++) {
        const int k0 = t << 6;
        __syncthreads();   // prior O-GEMM reads of Ks/Vs done (also orders Qs stores on t=0)

        #pragma unroll
        for (int c = 0; c < 4; c++) {
            int idx = tid + (c << 8);
            int row = idx >> 4;
            int col = (idx & 15) << 2;
            float4 kv = *reinterpret_cast<const float4*>(K + base + (size_t)(k0 + row) * NHD + col);
            Ks[(col + 0) * 68 + row] = kv.x; Ks[(col + 1) * 68 + row] = kv.y;
            Ks[(col + 2) * 68 + row] = kv.z; Ks[(col + 3) * 68 + row] = kv.w;
            float4 vv = *reinterpret_cast<const float4*>(V + base + (size_t)(k0 + row) * NHD + col);
            *reinterpret_cast<float4*>(&Vs[row * 68 + col]) = vv;
        }
        __syncthreads();

        // S = Q K^T
        float s_acc[4][4] = {};
        #pragma unroll
        for (int kk = 0; kk < 64; kk++) {
            float4 a4 = *reinterpret_cast<const float4*>(&Qs[kk * 68 + (ty << 2)]);
            float4 b4 = *reinterpret_cast<const float4*>(&Ks[kk * 68 + (tx << 2)]);
            float av[4] = {a4.x, a4.y, a4.z, a4.w};
            float bv[4] = {b4.x, b4.y, b4.z, b4.w};
            #pragma unroll
            for (int i = 0; i < 4; i++)
                #pragma unroll
                for (int j = 0; j < 4; j++)
                    s_acc[i][j] = fmaf(av[i], bv[j], s_acc[i][j]);
        }

        // scale + ALiBi + causal mask + online softmax
        float p[4][4];
        #pragma unroll
        for (int i = 0; i < 4; i++) {
            int q = q0 + (ty << 2) + i;
            float rowmax = -1e30f;
            #pragma unroll
            for (int j = 0; j < 4; j++) {
                int kc = k0 + (tx << 2) + j;
                float s = fmaf(s_acc[i][j], 0.125f, slope * (float)(kc - q));
                if (kc > q) s = -1e30f;
                s_acc[i][j] = s;
                rowmax = fmaxf(rowmax, s);
            }
            #pragma unroll
            for (int off = 1; off < 16; off <<= 1)
                rowmax = fmaxf(rowmax, __shfl_xor_sync(0xffffffffu, rowmax, off));
            float mnew = fmaxf(m_r[i], rowmax);
            float alpha = __expf(m_r[i] - mnew);
            float rsum = 0.0f;
            #pragma unroll
            for (int j = 0; j < 4; j++) {
                p[i][j] = __expf(s_acc[i][j] - mnew);
                rsum += p[i][j];
            }
            #pragma unroll
            for (int off = 1; off < 16; off <<= 1)
                rsum += __shfl_xor_sync(0xffffffffu, rsum, off);
            l_r[i] = l_r[i] * alpha + rsum;
            #pragma unroll
            for (int j = 0; j < 4; j++) acc_o[i][j] *= alpha;
            m_r[i] = mnew;
        }

        __syncthreads();   // everyone done reading Ks
        #pragma unroll
        for (int i = 0; i < 4; i++)
            #pragma unroll
            for (int j = 0; j < 4; j++)
                Ks[((tx << 2) + j) * 68 + (ty << 2) + i] = p[i][j];   // P[k][q]
        __syncthreads();

        // O += P V
        #pragma unroll
        for (int kk = 0; kk < 64; kk++) {
            float4 a4 = *reinterpret_cast<const float4*>(&Ks[kk * 68 + (ty << 2)]);
            float4 b4 = *reinterpret_cast<const float4*>(&Vs[kk * 68 + (tx << 2)]);
            float av[4] = {a4.x, a4.y, a4.z, a4.w};
            float bv[4] = {b4.x, b4.y, b4.z, b4.w};
            #pragma unroll
            for (int i = 0; i < 4; i++)
                #pragma unroll
                for (int j = 0; j < 4; j++)
                    acc_o[i][j] = fmaf(av[i], bv[j], acc_o[i][j]);
        }
    }

    // write (B,S,D)
    #pragma unroll
    for (int i = 0; i < 4; i++) {
        int q = q0 + (ty << 2) + i;
        float inv_l = 1.0f / l_r[i];
        float4 o4;
        o4.x = acc_o[i][0] * inv_l; o4.y = acc_o[i][1] * inv_l;
        o4.z = acc_o[i][2] * inv_l; o4.w = acc_o[i][3] * inv_l;
        *reinterpret_cast<float4*>(O + ((size_t)(b * NS + q)) * ND + h * NHD + (tx << 2)) = o4;
    }
}

// ---------------------------------------------------------------------------
// LayerNorm over last dim (768). One block per row, two-pass (matches ref).
// ---------------------------------------------------------------------------
__global__ __launch_bounds__(256) void ln_kernel(
    const float* __restrict__ X, const float* __restrict__ g,
    const float* __restrict__ be, float* __restrict__ Y)
{
    __shared__ float red[256];
    const int row = blockIdx.x;
    const int tid = threadIdx.x;
    const float* x = X + (size_t)row * ND;

    float s = 0.0f;
    for (int i = tid; i < ND; i += 256) s += x[i];
    red[tid] = s; __syncthreads();
    for (int off = 128; off > 0; off >>= 1) {
        if (tid < off) red[tid] += red[tid + off];
        __syncthreads();
    }
    float mu = red[0] * (1.0f / ND);
    __syncthreads();

    float vs = 0.0f;
    for (int i = tid; i < ND; i += 256) { float d = x[i] - mu; vs = fmaf(d, d, vs); }
    red[tid] = vs; __syncthreads();
    for (int off = 128; off > 0; off >>= 1) {
        if (tid < off) red[tid] += red[tid + off];
        __syncthreads();
    }
    float rstd = rsqrtf(red[0] * (1.0f / ND) + 1e-5f);

    for (int i = tid; i < ND; i += 256)
        Y[(size_t)row * ND + i] = (x[i] - mu) * rstd * g[i] + be[i];
}

// ---------------------------------------------------------------------------
extern "C" void kernel_launch(void* const* d_in, const int* in_sizes, int n_in,
                              void* d_out, int out_size)
{
    const float* x   = (const float*)d_in[0];
    // d_in[1] = mask, d_in[2] = alibi_bias  (computed analytically, not read)
    const float* wq  = (const float*)d_in[3];
    const float* bq  = (const float*)d_in[4];
    const float* wk  = (const float*)d_in[5];
    const float* bk  = (const float*)d_in[6];
    const float* wv  = (const float*)d_in[7];
    const float* bv  = (const float*)d_in[8];
    const float* wo  = (const float*)d_in[9];
    const float* bo  = (const float*)d_in[10];
    const float* w1  = (const float*)d_in[11];
    const float* b1  = (const float*)d_in[12];
    const float* w2  = (const float*)d_in[13];
    const float* b2  = (const float*)d_in[14];
    const float* g1  = (const float*)d_in[15];
    const float* be1 = (const float*)d_in[16];
    const float* g2  = (const float*)d_in[17];
    const float* be2 = (const float*)d_in[18];
    float* out = (float*)d_out;

    float *q_p, *k_p, *v_p, *attn_p, *tmp_p, *x1_p, *ff_p;
    cudaGetSymbolAddress((void**)&q_p,   g_q);
    cudaGetSymbolAddress((void**)&k_p,   g_k);
    cudaGetSymbolAddress((void**)&v_p,   g_v);
    cudaGetSymbolAddress((void**)&attn_p,g_attn);
    cudaGetSymbolAddress((void**)&tmp_p, g_tmp);
    cudaGetSymbolAddress((void**)&x1_p,  g_x1);
    cudaGetSymbolAddress((void**)&ff_p,  g_ff);

    const int attn_smem = 3 * 64 * 68 * (int)sizeof(float);   // 52224 B
    cudaFuncSetAttribute(attn_kernel, cudaFuncAttributeMaxDynamicSharedMemorySize, attn_smem);

    dim3 blk(256);

    // QKV projections -> (B,H,S,HD)
    gemm_kernel<<<dim3(ND/64,  NM/64), blk>>>(x, wq, bq, nullptr, q_p, NM, ND, ND, 0, 1);
    gemm_kernel<<<dim3(ND/64,  NM/64), blk>>>(x, wk, bk, nullptr, k_p, NM, ND, ND, 0, 1);
    gemm_kernel<<<dim3(ND/64,  NM/64), blk>>>(x, wv, bv, nullptr, v_p, NM, ND, ND, 0, 1);

    // attention -> (B,S,D)
    attn_kernel<<<dim3(NS/64, NB*NH), blk, attn_smem>>>(q_p, k_p, v_p, attn_p);

    // O projection + residual, then LN1
    gemm_kernel<<<dim3(ND/64,  NM/64), blk>>>(attn_p, wo, bo, x, tmp_p, NM, ND, ND, 0, 0);
    ln_kernel<<<NM, 256>>>(tmp_p, g1, be1, x1_p);

    // FFN
    gemm_kernel<<<dim3(NFF/64, NM/64), blk>>>(x1_p, w1, b1, nullptr, ff_p, NM, NFF, ND, 1, 0);
    gemm_kernel<<<dim3(ND/64,  NM/64), blk>>>(ff_p, w2, b2, x1_p, tmp_p, NM, ND, NFF, 0, 0);
    ln_kernel<<<NM, 256>>>(tmp_p, g2, be2, out);
}

// round 4
// speedup vs baseline: 2.2752x; 2.2752x over previous
#include <cuda_runtime.h>
#include <cstdint>

#define NB 2
#define NS 2048
#define ND 768
#define NH 12
#define NHD 64
#define NFF 3072
#define NM (NB*NS)   // 4096 rows

// ---------------- scratch (static device allocations, allowed) ----------------
__device__ float g_q[NB*NH*NS*NHD];
__device__ float g_k[NB*NH*NS*NHD];
__device__ float g_v[NB*NH*NS*NHD];
__device__ float g_attn[NM*ND];
__device__ float g_tmp[NM*ND];
__device__ float g_x1[NM*ND];
__device__ float g_ff[(size_t)NM*NFF];

// ===========================================================================
// TF32 tensor-core GEMM:  C[m,n] = sum_k A[m,k]*W[n,k] (+bias)(+relu)(+res)
// 128x128 CTA tile, 8 warps (2x4 -> 64x32 warp tiles), BK=32.
// cp.async double-buffered smem; ldmatrix.x4 for BOTH operands (conflict-free
// with row stride 36 words); cvt.rna.tf32 applied on fragments.
// ===========================================================================
#define BK 32
#define SPAD 36                 // smem row stride (words)
#define SBUF (128*SPAD)         // words per buffer (4608)
#define GEMM_SMEM (4*SBUF*4)    // A0,A1,W0,W1 = 73728 bytes

__device__ __forceinline__ uint32_t f2tf32(float x) {
    uint32_t r;
    asm("cvt.rna.tf32.f32 %0, %1;" : "=r"(r) : "f"(x));
    return r;
}

__device__ __forceinline__ void ldsm4(uint32_t& r0, uint32_t& r1,
                                      uint32_t& r2, uint32_t& r3, uint32_t addr) {
    asm volatile("ldmatrix.sync.aligned.m8n8.x4.shared.b16 {%0,%1,%2,%3}, [%4];"
                 : "=r"(r0), "=r"(r1), "=r"(r2), "=r"(r3) : "r"(addr));
}

__device__ __forceinline__ void mma_tf32(float* c, const uint32_t* a, const uint32_t* b) {
    asm volatile(
        "mma.sync.aligned.m16n8k8.row.col.f32.tf32.tf32.f32 "
        "{%0,%1,%2,%3}, {%4,%5,%6,%7}, {%8,%9}, {%0,%1,%2,%3};"
        : "+f"(c[0]), "+f"(c[1]), "+f"(c[2]), "+f"(c[3])
        : "r"(a[0]), "r"(a[1]), "r"(a[2]), "r"(a[3]), "r"(b[0]), "r"(b[1]));
}

__device__ __forceinline__ void cp16(uint32_t daddr, const void* gaddr) {
    asm volatile("cp.async.cg.shared.global [%0], [%1], 16;" :: "r"(daddr), "l"(gaddr));
}

__global__ __launch_bounds__(256, 2) void gemm_tc(
    const float* __restrict__ A, const float* __restrict__ W,
    const float* __restrict__ bias, const float* __restrict__ res,
    float* __restrict__ C, int M, int N, int K, int relu, int headsplit)
{
    extern __shared__ uint32_t sm[];
    const int tid = threadIdx.x, lane = tid & 31, warp = tid >> 5;
    const int wm = (warp & 1) << 6;      // 0 / 64
    const int wn = (warp >> 1) << 5;     // 0..96
    const int m0 = blockIdx.y << 7, n0 = blockIdx.x << 7;

    // --- gmem -> smem copy mapping: thread covers 4 rows (stride 32) x 16B ---
    const int lr = tid >> 3;             // 0..31 base row
    const int lc = (tid & 7) << 2;       // col (floats)
    const float* Ag = A + (size_t)(m0 + lr) * K + lc;
    const float* Wg = W + (size_t)(n0 + lr) * K + lc;
    const int sidx = lr * SPAD + lc;     // + c*32*SPAD

    const uint32_t s_base = (uint32_t)__cvta_generic_to_shared(sm);

    // --- ldmatrix per-thread byte offsets ---
    // A fragments (m16n8k8, row-major A): x4 tiles {g,t},{g+8,t},{g,t+4},{g+8,t+4}
    const int a_row = wm + (lane & 15);
    const int a_col = (lane >> 4) << 2;
    uint32_t a_off[4];
    #pragma unroll
    for (int mi = 0; mi < 4; mi++)
        a_off[mi] = (uint32_t)(((a_row + mi * 16) * SPAD + a_col) << 2);
    // B fragments: one x4 covers two n8 frags (W stored [n][k])
    const int b_row = wn + (lane & 7) + ((lane >> 4) << 3);
    const int b_col = ((lane >> 3) & 1) << 2;
    uint32_t b_off[2];
    #pragma unroll
    for (int j = 0; j < 2; j++)
        b_off[j] = (uint32_t)(((b_row + j * 16) * SPAD + b_col) << 2);

    float acc[4][4][4] = {};

    const int nt = K / BK;

    // issue one tile's cp.asyncs into buffer `buf`
    auto issue = [&](int t, int buf) {
        const int k0 = t * BK;
        #pragma unroll
        for (int c = 0; c < 4; c++) {
            uint32_t da = s_base + (uint32_t)((buf * SBUF + sidx + c * 32 * SPAD) << 2);
            uint32_t dw = s_base + (uint32_t)(((2 + buf) * SBUF + sidx + c * 32 * SPAD) << 2);
            cp16(da, Ag + (size_t)c * 32 * K + k0);
            cp16(dw, Wg + (size_t)c * 32 * K + k0);
        }
        asm volatile("cp.async.commit_group;");
    };

    issue(0, 0);

    for (int t = 0; t < nt; t++) {
        if (t + 1 < nt) {
            issue(t + 1, (t + 1) & 1);
            asm volatile("cp.async.wait_group 1;");
        } else {
            asm volatile("cp.async.wait_group 0;");
        }
        __syncthreads();

        const uint32_t abase = s_base + (uint32_t)(((t & 1) * SBUF) << 2);
        const uint32_t bbase = s_base + (uint32_t)(((2 + (t & 1)) * SBUF) << 2);

        #pragma unroll
        for (int kk = 0; kk < 4; kk++) {
            uint32_t af[4][4], bf[4][2];
            #pragma unroll
            for (int mi = 0; mi < 4; mi++)
                ldsm4(af[mi][0], af[mi][1], af[mi][2], af[mi][3],
                      abase + a_off[mi] + kk * 32);
            #pragma unroll
            for (int j = 0; j < 2; j++)
                ldsm4(bf[2*j][0], bf[2*j][1], bf[2*j+1][0], bf[2*j+1][1],
                      bbase + b_off[j] + kk * 32);
            // round to tf32
            #pragma unroll
            for (int mi = 0; mi < 4; mi++)
                #pragma unroll
                for (int r = 0; r < 4; r++)
                    af[mi][r] = f2tf32(__uint_as_float(af[mi][r]));
            #pragma unroll
            for (int nj = 0; nj < 4; nj++) {
                bf[nj][0] = f2tf32(__uint_as_float(bf[nj][0]));
                bf[nj][1] = f2tf32(__uint_as_float(bf[nj][1]));
            }
            #pragma unroll
            for (int mi = 0; mi < 4; mi++)
                #pragma unroll
                for (int nj = 0; nj < 4; nj++)
                    mma_tf32(acc[mi][nj], af[mi], bf[nj]);
        }
        __syncthreads();
    }

    // ------------------------------ epilogue -------------------------------
    #pragma unroll
    for (int mi = 0; mi < 4; mi++) {
        const int m = m0 + wm + mi * 16 + (lane >> 2);
        #pragma unroll
        for (int nj = 0; nj < 4; nj++) {
            const int n = n0 + wn + nj * 8 + ((lane & 3) << 1);
            const float b0v = bias[n], b1v = bias[n + 1];
            #pragma unroll
            for (int r = 0; r < 2; r++) {
                const int mm = m + r * 8;
                float v0 = acc[mi][nj][r * 2 + 0] + b0v;
                float v1 = acc[mi][nj][r * 2 + 1] + b1v;
                if (relu) { v0 = fmaxf(v0, 0.0f); v1 = fmaxf(v1, 0.0f); }
                if (res) {
                    v0 += res[(size_t)mm * N + n];
                    v1 += res[(size_t)mm * N + n + 1];
                }
                if (headsplit) {
                    int h = n >> 6, hd = n & 63;
                    int b = mm >> 11, s = mm & (NS - 1);
                    *reinterpret_cast<float2*>(
                        &C[(((size_t)(b * NH + h)) * NS + s) * NHD + hd]) =
                        make_float2(v0, v1);
                } else {
                    *reinterpret_cast<float2*>(&C[(size_t)mm * N + n]) =
                        make_float2(v0, v1);
                }
            }
        }
    }
}

// ---------------------------------------------------------------------------
// Flash attention, fp32 (unchanged from the passing baseline).
// ---------------------------------------------------------------------------
__global__ __launch_bounds__(256) void attn_kernel(
    const float* __restrict__ Q, const float* __restrict__ K,
    const float* __restrict__ V, float* __restrict__ O)
{
    extern __shared__ __align__(16) float smf[];
    float* Qs = smf;                // [64][68]  (transposed: [d][q])
    float* Ks = smf + 64 * 68;      // [64][68]  (transposed: [d][k]), reused as P[k][q]
    float* Vs = smf + 2 * 64 * 68;  // [64][68]  (natural:   [k][d])

    const int tid = threadIdx.x;
    const int ty = tid >> 4, tx = tid & 15;
    const int q0 = blockIdx.x << 6;
    const int bh = blockIdx.y;
    const int h  = bh % NH;
    const int b  = bh / NH;
    const size_t base = (size_t)bh * NS * NHD;
    const float slope = exp2f(-(8.0f / NH) * (float)(h + 1));

    #pragma unroll
    for (int c = 0; c < 4; c++) {
        int idx = tid + (c << 8);
        int row = idx >> 4;
        int col = (idx & 15) << 2;
        float4 v = *reinterpret_cast<const float4*>(Q + base + (size_t)(q0 + row) * NHD + col);
        Qs[(col + 0) * 68 + row] = v.x; Qs[(col + 1) * 68 + row] = v.y;
        Qs[(col + 2) * 68 + row] = v.z; Qs[(col + 3) * 68 + row] = v.w;
    }

    float m_r[4], l_r[4];
    float acc_o[4][4] = {};
    #pragma unroll
    for (int i = 0; i < 4; i++) { m_r[i] = -1e30f; l_r[i] = 0.0f; }

    const int nt = (q0 >> 6) + 1;
    for (int t = 0; t < nt; t++) {
        const int k0 = t << 6;
        __syncthreads();

        #pragma unroll
        for (int c = 0; c < 4; c++) {
            int idx = tid + (c << 8);
            int row = idx >> 4;
            int col = (idx & 15) << 2;
            float4 kv = *reinterpret_cast<const float4*>(K + base + (size_t)(k0 + row) * NHD + col);
            Ks[(col + 0) * 68 + row] = kv.x; Ks[(col + 1) * 68 + row] = kv.y;
            Ks[(col + 2) * 68 + row] = kv.z; Ks[(col + 3) * 68 + row] = kv.w;
            float4 vv = *reinterpret_cast<const float4*>(V + base + (size_t)(k0 + row) * NHD + col);
            *reinterpret_cast<float4*>(&Vs[row * 68 + col]) = vv;
        }
        __syncthreads();

        float s_acc[4][4] = {};
        #pragma unroll
        for (int kk = 0; kk < 64; kk++) {
            float4 a4 = *reinterpret_cast<const float4*>(&Qs[kk * 68 + (ty << 2)]);
            float4 b4 = *reinterpret_cast<const float4*>(&Ks[kk * 68 + (tx << 2)]);
            float av[4] = {a4.x, a4.y, a4.z, a4.w};
            float bv[4] = {b4.x, b4.y, b4.z, b4.w};
            #pragma unroll
            for (int i = 0; i < 4; i++)
                #pragma unroll
                for (int j = 0; j < 4; j++)
                    s_acc[i][j] = fmaf(av[i], bv[j], s_acc[i][j]);
        }

        float p[4][4];
        #pragma unroll
        for (int i = 0; i < 4; i++) {
            int q = q0 + (ty << 2) + i;
            float rowmax = -1e30f;
            #pragma unroll
            for (int j = 0; j < 4; j++) {
                int kc = k0 + (tx << 2) + j;
                float s = fmaf(s_acc[i][j], 0.125f, slope * (float)(kc - q));
                if (kc > q) s = -1e30f;
                s_acc[i][j] = s;
                rowmax = fmaxf(rowmax, s);
            }
            #pragma unroll
            for (int off = 1; off < 16; off <<= 1)
                rowmax = fmaxf(rowmax, __shfl_xor_sync(0xffffffffu, rowmax, off));
            float mnew = fmaxf(m_r[i], rowmax);
            float alpha = __expf(m_r[i] - mnew);
            float rsum = 0.0f;
            #pragma unroll
            for (int j = 0; j < 4; j++) {
                p[i][j] = __expf(s_acc[i][j] - mnew);
                rsum += p[i][j];
            }
            #pragma unroll
            for (int off = 1; off < 16; off <<= 1)
                rsum += __shfl_xor_sync(0xffffffffu, rsum, off);
            l_r[i] = l_r[i] * alpha + rsum;
            #pragma unroll
            for (int j = 0; j < 4; j++) acc_o[i][j] *= alpha;
            m_r[i] = mnew;
        }

        __syncthreads();
        #pragma unroll
        for (int i = 0; i < 4; i++)
            #pragma unroll
            for (int j = 0; j < 4; j++)
                Ks[((tx << 2) + j) * 68 + (ty << 2) + i] = p[i][j];
        __syncthreads();

        #pragma unroll
        for (int kk = 0; kk < 64; kk++) {
            float4 a4 = *reinterpret_cast<const float4*>(&Ks[kk * 68 + (ty << 2)]);
            float4 b4 = *reinterpret_cast<const float4*>(&Vs[kk * 68 + (tx << 2)]);
            float av[4] = {a4.x, a4.y, a4.z, a4.w};
            float bv[4] = {b4.x, b4.y, b4.z, b4.w};
            #pragma unroll
            for (int i = 0; i < 4; i++)
                #pragma unroll
                for (int j = 0; j < 4; j++)
                    acc_o[i][j] = fmaf(av[i], bv[j], acc_o[i][j]);
        }
    }

    #pragma unroll
    for (int i = 0; i < 4; i++) {
        int q = q0 + (ty << 2) + i;
        float inv_l = 1.0f / l_r[i];
        float4 o4;
        o4.x = acc_o[i][0] * inv_l; o4.y = acc_o[i][1] * inv_l;
        o4.z = acc_o[i][2] * inv_l; o4.w = acc_o[i][3] * inv_l;
        *reinterpret_cast<float4*>(O + ((size_t)(b * NS + q)) * ND + h * NHD + (tx << 2)) = o4;
    }
}

// ---------------------------------------------------------------------------
// LayerNorm over last dim (768). One block per row, two-pass (matches ref).
// ---------------------------------------------------------------------------
__global__ __launch_bounds__(256) void ln_kernel(
    const float* __restrict__ X, const float* __restrict__ g,
    const float* __restrict__ be, float* __restrict__ Y)
{
    __shared__ float red[256];
    const int row = blockIdx.x;
    const int tid = threadIdx.x;
    const float* x = X + (size_t)row * ND;

    float s = 0.0f;
    for (int i = tid; i < ND; i += 256) s += x[i];
    red[tid] = s; __syncthreads();
    for (int off = 128; off > 0; off >>= 1) {
        if (tid < off) red[tid] += red[tid + off];
        __syncthreads();
    }
    float mu = red[0] * (1.0f / ND);
    __syncthreads();

    float vs = 0.0f;
    for (int i = tid; i < ND; i += 256) { float d = x[i] - mu; vs = fmaf(d, d, vs); }
    red[tid] = vs; __syncthreads();
    for (int off = 128; off > 0; off >>= 1) {
        if (tid < off) red[tid] += red[tid + off];
        __syncthreads();
    }
    float rstd = rsqrtf(red[0] * (1.0f / ND) + 1e-5f);

    for (int i = tid; i < ND; i += 256)
        Y[(size_t)row * ND + i] = (x[i] - mu) * rstd * g[i] + be[i];
}

// ---------------------------------------------------------------------------
extern "C" void kernel_launch(void* const* d_in, const int* in_sizes, int n_in,
                              void* d_out, int out_size)
{
    const float* x   = (const float*)d_in[0];
    // d_in[1] = mask, d_in[2] = alibi_bias  (computed analytically, not read)
    const float* wq  = (const float*)d_in[3];
    const float* bq  = (const float*)d_in[4];
    const float* wk  = (const float*)d_in[5];
    const float* bk  = (const float*)d_in[6];
    const float* wv  = (const float*)d_in[7];
    const float* bv  = (const float*)d_in[8];
    const float* wo  = (const float*)d_in[9];
    const float* bo  = (const float*)d_in[10];
    const float* w1  = (const float*)d_in[11];
    const float* b1  = (const float*)d_in[12];
    const float* w2  = (const float*)d_in[13];
    const float* b2  = (const float*)d_in[14];
    const float* g1  = (const float*)d_in[15];
    const float* be1 = (const float*)d_in[16];
    const float* g2  = (const float*)d_in[17];
    const float* be2 = (const float*)d_in[18];
    float* out = (float*)d_out;

    float *q_p, *k_p, *v_p, *attn_p, *tmp_p, *x1_p, *ff_p;
    cudaGetSymbolAddress((void**)&q_p,   g_q);
    cudaGetSymbolAddress((void**)&k_p,   g_k);
    cudaGetSymbolAddress((void**)&v_p,   g_v);
    cudaGetSymbolAddress((void**)&attn_p,g_attn);
    cudaGetSymbolAddress((void**)&tmp_p, g_tmp);
    cudaGetSymbolAddress((void**)&x1_p,  g_x1);
    cudaGetSymbolAddress((void**)&ff_p,  g_ff);

    const int attn_smem = 3 * 64 * 68 * (int)sizeof(float);   // 52224 B
    cudaFuncSetAttribute(attn_kernel, cudaFuncAttributeMaxDynamicSharedMemorySize, attn_smem);
    cudaFuncSetAttribute(gemm_tc, cudaFuncAttributeMaxDynamicSharedMemorySize, GEMM_SMEM);

    dim3 blk(256);

    // QKV projections -> (B,H,S,HD)
    gemm_tc<<<dim3(ND/128,  NM/128), blk, GEMM_SMEM>>>(x, wq, bq, nullptr, q_p, NM, ND, ND, 0, 1);
    gemm_tc<<<dim3(ND/128,  NM/128), blk, GEMM_SMEM>>>(x, wk, bk, nullptr, k_p, NM, ND, ND, 0, 1);
    gemm_tc<<<dim3(ND/128,  NM/128), blk, GEMM_SMEM>>>(x, wv, bv, nullptr, v_p, NM, ND, ND, 0, 1);

    // attention -> (B,S,D)
    attn_kernel<<<dim3(NS/64, NB*NH), blk, attn_smem>>>(q_p, k_p, v_p, attn_p);

    // O projection + residual, then LN1
    gemm_tc<<<dim3(ND/128,  NM/128), blk, GEMM_SMEM>>>(attn_p, wo, bo, x, tmp_p, NM, ND, ND, 0, 0);
    ln_kernel<<<NM, 256>>>(tmp_p, g1, be1, x1_p);

    // FFN
    gemm_tc<<<dim3(NFF/128, NM/128), blk, GEMM_SMEM>>>(x1_p, w1, b1, nullptr, ff_p, NM, NFF, ND, 1, 0);
    gemm_tc<<<dim3(ND/128,  NM/128), blk, GEMM_SMEM>>>(ff_p, w2, b2, x1_p, tmp_p, NM, ND, NFF, 0, 0);
    ln_kernel<<<NM, 256>>>(tmp_p, g2, be2, out);
}

// round 5
// speedup vs baseline: 3.1515x; 1.3851x over previous
#include <cuda_runtime.h>
#include <cstdint>

#define NB 2
#define NS 2048
#define ND 768
#define NH 12
#define NHD 64
#define NFF 3072
#define NM (NB*NS)   // 4096 rows

// ---------------- scratch (static device allocations, allowed) ----------------
__device__ float g_q[NB*NH*NS*NHD];
__device__ float g_k[NB*NH*NS*NHD];
__device__ float g_v[NB*NH*NS*NHD];
__device__ float g_attn[NM*ND];
__device__ float g_tmp[NM*ND];
__device__ float g_x1[NM*ND];
__device__ float g_ff[(size_t)NM*NFF];

// ---------------- common tensor-core helpers ----------------
__device__ __forceinline__ uint32_t f2tf32(float x) {
    uint32_t r;
    asm("cvt.rna.tf32.f32 %0, %1;" : "=r"(r) : "f"(x));
    return r;
}

__device__ __forceinline__ void ldsm4(uint32_t& r0, uint32_t& r1,
                                      uint32_t& r2, uint32_t& r3, uint32_t addr) {
    asm volatile("ldmatrix.sync.aligned.m8n8.x4.shared.b16 {%0,%1,%2,%3}, [%4];"
                 : "=r"(r0), "=r"(r1), "=r"(r2), "=r"(r3) : "r"(addr));
}

__device__ __forceinline__ void mma_tf32(float* c, const uint32_t* a, const uint32_t* b) {
    asm volatile(
        "mma.sync.aligned.m16n8k8.row.col.f32.tf32.tf32.f32 "
        "{%0,%1,%2,%3}, {%4,%5,%6,%7}, {%8,%9}, {%0,%1,%2,%3};"
        : "+f"(c[0]), "+f"(c[1]), "+f"(c[2]), "+f"(c[3])
        : "r"(a[0]), "r"(a[1]), "r"(a[2]), "r"(a[3]), "r"(b[0]), "r"(b[1]));
}

__device__ __forceinline__ void cp16(uint32_t daddr, const void* gaddr) {
    asm volatile("cp.async.cg.shared.global [%0], [%1], 16;" :: "r"(daddr), "l"(gaddr));
}

// ===========================================================================
// TF32 tensor-core GEMM (unchanged from R3):
// C[m,n] = sum_k A[m,k]*W[n,k] (+bias)(+relu)(+res)
// ===========================================================================
#define BK 32
#define SPAD 36
#define SBUF (128*SPAD)
#define GEMM_SMEM (4*SBUF*4)

__global__ __launch_bounds__(256, 2) void gemm_tc(
    const float* __restrict__ A, const float* __restrict__ W,
    const float* __restrict__ bias, const float* __restrict__ res,
    float* __restrict__ C, int M, int N, int K, int relu, int headsplit)
{
    extern __shared__ uint32_t sm[];
    const int tid = threadIdx.x, lane = tid & 31, warp = tid >> 5;
    const int wm = (warp & 1) << 6;
    const int wn = (warp >> 1) << 5;
    const int m0 = blockIdx.y << 7, n0 = blockIdx.x << 7;

    const int lr = tid >> 3;
    const int lc = (tid & 7) << 2;
    const float* Ag = A + (size_t)(m0 + lr) * K + lc;
    const float* Wg = W + (size_t)(n0 + lr) * K + lc;
    const int sidx = lr * SPAD + lc;

    const uint32_t s_base = (uint32_t)__cvta_generic_to_shared(sm);

    const int a_row = wm + (lane & 15);
    const int a_col = (lane >> 4) << 2;
    uint32_t a_off[4];
    #pragma unroll
    for (int mi = 0; mi < 4; mi++)
        a_off[mi] = (uint32_t)(((a_row + mi * 16) * SPAD + a_col) << 2);
    const int b_row = wn + (lane & 7) + ((lane >> 4) << 3);
    const int b_col = ((lane >> 3) & 1) << 2;
    uint32_t b_off[2];
    #pragma unroll
    for (int j = 0; j < 2; j++)
        b_off[j] = (uint32_t)(((b_row + j * 16) * SPAD + b_col) << 2);

    float acc[4][4][4] = {};
    const int nt = K / BK;

    auto issue = [&](int t, int buf) {
        const int k0 = t * BK;
        #pragma unroll
        for (int c = 0; c < 4; c++) {
            uint32_t da = s_base + (uint32_t)((buf * SBUF + sidx + c * 32 * SPAD) << 2);
            uint32_t dw = s_base + (uint32_t)(((2 + buf) * SBUF + sidx + c * 32 * SPAD) << 2);
            cp16(da, Ag + (size_t)c * 32 * K + k0);
            cp16(dw, Wg + (size_t)c * 32 * K + k0);
        }
        asm volatile("cp.async.commit_group;");
    };

    issue(0, 0);

    for (int t = 0; t < nt; t++) {
        if (t + 1 < nt) {
            issue(t + 1, (t + 1) & 1);
            asm volatile("cp.async.wait_group 1;");
        } else {
            asm volatile("cp.async.wait_group 0;");
        }
        __syncthreads();

        const uint32_t abase = s_base + (uint32_t)(((t & 1) * SBUF) << 2);
        const uint32_t bbase = s_base + (uint32_t)(((2 + (t & 1)) * SBUF) << 2);

        #pragma unroll
        for (int kk = 0; kk < 4; kk++) {
            uint32_t af[4][4], bf[4][2];
            #pragma unroll
            for (int mi = 0; mi < 4; mi++)
                ldsm4(af[mi][0], af[mi][1], af[mi][2], af[mi][3],
                      abase + a_off[mi] + kk * 32);
            #pragma unroll
            for (int j = 0; j < 2; j++)
                ldsm4(bf[2*j][0], bf[2*j][1], bf[2*j+1][0], bf[2*j+1][1],
                      bbase + b_off[j] + kk * 32);
            #pragma unroll
            for (int mi = 0; mi < 4; mi++)
                #pragma unroll
                for (int r = 0; r < 4; r++)
                    af[mi][r] = f2tf32(__uint_as_float(af[mi][r]));
            #pragma unroll
            for (int nj = 0; nj < 4; nj++) {
                bf[nj][0] = f2tf32(__uint_as_float(bf[nj][0]));
                bf[nj][1] = f2tf32(__uint_as_float(bf[nj][1]));
            }
            #pragma unroll
            for (int mi = 0; mi < 4; mi++)
                #pragma unroll
                for (int nj = 0; nj < 4; nj++)
                    mma_tf32(acc[mi][nj], af[mi], bf[nj]);
        }
        __syncthreads();
    }

    #pragma unroll
    for (int mi = 0; mi < 4; mi++) {
        const int m = m0 + wm + mi * 16 + (lane >> 2);
        #pragma unroll
        for (int nj = 0; nj < 4; nj++) {
            const int n = n0 + wn + nj * 8 + ((lane & 3) << 1);
            const float b0v = bias[n], b1v = bias[n + 1];
            #pragma unroll
            for (int r = 0; r < 2; r++) {
                const int mm = m + r * 8;
                float v0 = acc[mi][nj][r * 2 + 0] + b0v;
                float v1 = acc[mi][nj][r * 2 + 1] + b1v;
                if (relu) { v0 = fmaxf(v0, 0.0f); v1 = fmaxf(v1, 0.0f); }
                if (res) {
                    v0 += res[(size_t)mm * N + n];
                    v1 += res[(size_t)mm * N + n + 1];
                }
                if (headsplit) {
                    int h = n >> 6, hd = n & 63;
                    int b = mm >> 11, s = mm & (NS - 1);
                    *reinterpret_cast<float2*>(
                        &C[(((size_t)(b * NH + h)) * NS + s) * NHD + hd]) =
                        make_float2(v0, v1);
                } else {
                    *reinterpret_cast<float2*>(&C[(size_t)mm * N + n]) =
                        make_float2(v0, v1);
                }
            }
        }
    }
}

// ===========================================================================
// Tensor-core flash attention (tf32). 64q x 64k tiles, 128 threads / 4 warps.
// Warp w owns q rows [16w,16w+16) x ALL 64 keys -> no cross-warp reductions.
// S = Q K^T and O += P V both via mma.m16n8k8.tf32.
// Smem: Qs (reused as Ps after Q-frag extraction), Ks [key][d], Vt [d][key].
// Stride 68 words => conflict-free ldmatrix (68 mod 32 = 4).
// ===========================================================================
#define ASTRIDE 68
#define ATT_SMEM (3*64*ASTRIDE*4)   // 52224 bytes

__global__ __launch_bounds__(128) void attn_tc(
    const float* __restrict__ Q, const float* __restrict__ K,
    const float* __restrict__ V, float* __restrict__ O)
{
    extern __shared__ float smf[];
    float* Qs = smf;                     // [64][68]  [q][d], later reused as P [q][key]
    float* Ks = smf + 64 * ASTRIDE;      // [64][68]  [key][d]
    float* Vt = smf + 2 * 64 * ASTRIDE;  // [64][68]  [d][key]

    const int tid = threadIdx.x, lane = tid & 31, warp = tid >> 5;
    const int q0 = (int)(gridDim.x - 1 - blockIdx.x) << 6;   // heavy CTAs first
    const int bh = blockIdx.y;
    const int h = bh % NH, b = bh / NH;
    const size_t base = (size_t)bh * NS * NHD;
    const float slope = exp2f(-(8.0f / NH) * (float)(h + 1));

    const uint32_t s_base = (uint32_t)__cvta_generic_to_shared(smf);
    const uint32_t qs_b = s_base;                       // also Ps
    const uint32_t ks_b = s_base + 64 * ASTRIDE * 4;
    const uint32_t vt_b = s_base + 2 * 64 * ASTRIDE * 4;

    // A-fragment ldmatrix offset (rows = this warp's 16 q rows)
    const int a_row = (warp << 4) + (lane & 15);
    const uint32_t a_off = (uint32_t)((a_row * ASTRIDE + ((lane >> 4) << 2)) << 2);
    // B-fragment ldmatrix offsets (4 x4-loads cover 8 n-frags = 64 rows)
    const int b_row = (lane & 7) + ((lane >> 4) << 3);
    const int b_colb = (((lane >> 3) & 1) << 2) << 2;
    uint32_t b_off[4];
    #pragma unroll
    for (int jj = 0; jj < 4; jj++)
        b_off[jj] = (uint32_t)(((b_row + 16 * jj) * ASTRIDE) << 2) + b_colb;

    // ---- load Q tile [q][d] row-major, extract A-fragments once ----
    #pragma unroll
    for (int c = 0; c < 8; c++) {
        int idx = tid + (c << 7);
        int row = idx >> 4;
        int colf = (idx & 15) << 2;
        float4 v = *reinterpret_cast<const float4*>(Q + base + (size_t)(q0 + row) * NHD + colf);
        *reinterpret_cast<float4*>(&Qs[row * ASTRIDE + colf]) = v;
    }
    __syncthreads();

    uint32_t qf[8][4];
    #pragma unroll
    for (int kk = 0; kk < 8; kk++) {
        ldsm4(qf[kk][0], qf[kk][1], qf[kk][2], qf[kk][3], qs_b + a_off + kk * 32);
        #pragma unroll
        for (int r = 0; r < 4; r++) qf[kk][r] = f2tf32(__uint_as_float(qf[kk][r]));
    }

    float acc_o[8][4] = {};
    float m_r[2] = {-1e30f, -1e30f};
    float l_r[2] = {0.0f, 0.0f};
    const int qrow = q0 + (warp << 4) + (lane >> 2);

    const int nt = (q0 >> 6) + 1;
    for (int t = 0; t < nt; t++) {
        const int k0 = t << 6;
        __syncthreads();   // prior reads of Ks/Vt (and for t=0: Q-frag extraction) done

        // load K [key][d] and V transposed [d][key]
        #pragma unroll
        for (int c = 0; c < 8; c++) {
            int idx = tid + (c << 7);
            int row = idx >> 4;
            int colf = (idx & 15) << 2;
            float4 kv = *reinterpret_cast<const float4*>(K + base + (size_t)(k0 + row) * NHD + colf);
            *reinterpret_cast<float4*>(&Ks[row * ASTRIDE + colf]) = kv;
            float4 vv = *reinterpret_cast<const float4*>(V + base + (size_t)(k0 + row) * NHD + colf);
            Vt[(colf + 0) * ASTRIDE + row] = vv.x;
            Vt[(colf + 1) * ASTRIDE + row] = vv.y;
            Vt[(colf + 2) * ASTRIDE + row] = vv.z;
            Vt[(colf + 3) * ASTRIDE + row] = vv.w;
        }
        __syncthreads();

        // ---- S = Q K^T ----
        float sc[8][4] = {};
        #pragma unroll
        for (int kk = 0; kk < 8; kk++) {
            uint32_t bf[8][2];
            #pragma unroll
            for (int jj = 0; jj < 4; jj++)
                ldsm4(bf[2*jj][0], bf[2*jj][1], bf[2*jj+1][0], bf[2*jj+1][1],
                      ks_b + b_off[jj] + kk * 32);
            #pragma unroll
            for (int j = 0; j < 8; j++) {
                bf[j][0] = f2tf32(__uint_as_float(bf[j][0]));
                bf[j][1] = f2tf32(__uint_as_float(bf[j][1]));
            }
            #pragma unroll
            for (int j = 0; j < 8; j++)
                mma_tf32(sc[j], qf[kk], bf[j]);
        }

        // ---- scale + alibi + causal + online softmax (per 2 rows/thread) ----
        #pragma unroll
        for (int r = 0; r < 2; r++) {
            const int q = qrow + r * 8;
            float mx = -1e30f;
            #pragma unroll
            for (int j = 0; j < 8; j++) {
                int kc = k0 + 8 * j + ((lane & 3) << 1);
                float s0 = fmaf(sc[j][2*r+0], 0.125f, slope * (float)(kc - q));
                float s1 = fmaf(sc[j][2*r+1], 0.125f, slope * (float)(kc + 1 - q));
                if (kc > q)     s0 = -1e30f;
                if (kc + 1 > q) s1 = -1e30f;
                sc[j][2*r+0] = s0; sc[j][2*r+1] = s1;
                mx = fmaxf(mx, fmaxf(s0, s1));
            }
            mx = fmaxf(mx, __shfl_xor_sync(0xffffffffu, mx, 1));
            mx = fmaxf(mx, __shfl_xor_sync(0xffffffffu, mx, 2));
            const float mnew = fmaxf(m_r[r], mx);
            const float alpha = __expf(m_r[r] - mnew);
            float sum = 0.0f;
            #pragma unroll
            for (int j = 0; j < 8; j++) {
                float p0 = __expf(sc[j][2*r+0] - mnew);
                float p1 = __expf(sc[j][2*r+1] - mnew);
                sc[j][2*r+0] = p0; sc[j][2*r+1] = p1;
                sum += p0 + p1;
            }
            sum += __shfl_xor_sync(0xffffffffu, sum, 1);
            sum += __shfl_xor_sync(0xffffffffu, sum, 2);
            l_r[r] = l_r[r] * alpha + sum;
            #pragma unroll
            for (int j = 0; j < 8; j++) {
                acc_o[j][2*r+0] *= alpha;
                acc_o[j][2*r+1] *= alpha;
            }
            m_r[r] = mnew;
        }

        // ---- write P to smem (Qs region); warp-private rows ----
        __syncwarp();
        #pragma unroll
        for (int r = 0; r < 2; r++) {
            const int rl = (warp << 4) + (lane >> 2) + r * 8;
            #pragma unroll
            for (int j = 0; j < 8; j++) {
                *reinterpret_cast<float2*>(&Qs[rl * ASTRIDE + 8 * j + ((lane & 3) << 1)]) =
                    make_float2(sc[j][2*r+0], sc[j][2*r+1]);
            }
        }
        __syncwarp();

        // ---- O += P V ----
        #pragma unroll
        for (int kk = 0; kk < 8; kk++) {
            uint32_t pf[4];
            ldsm4(pf[0], pf[1], pf[2], pf[3], qs_b + a_off + kk * 32);
            #pragma unroll
            for (int r = 0; r < 4; r++) pf[r] = f2tf32(__uint_as_float(pf[r]));
            uint32_t bf[8][2];
            #pragma unroll
            for (int jj = 0; jj < 4; jj++)
                ldsm4(bf[2*jj][0], bf[2*jj][1], bf[2*jj+1][0], bf[2*jj+1][1],
                      vt_b + b_off[jj] + kk * 32);
            #pragma unroll
            for (int j = 0; j < 8; j++) {
                bf[j][0] = f2tf32(__uint_as_float(bf[j][0]));
                bf[j][1] = f2tf32(__uint_as_float(bf[j][1]));
            }
            #pragma unroll
            for (int j = 0; j < 8; j++)
                mma_tf32(acc_o[j], pf, bf[j]);
        }
    }

    // ---- normalize and write O into (B,S,D) ----
    #pragma unroll
    for (int r = 0; r < 2; r++) {
        const int q = qrow + r * 8;
        const float inv = 1.0f / l_r[r];
        #pragma unroll
        for (int j = 0; j < 8; j++) {
            const int d = (h << 6) + 8 * j + ((lane & 3) << 1);
            *reinterpret_cast<float2*>(&O[((size_t)(b * NS + q)) * ND + d]) =
                make_float2(acc_o[j][2*r+0] * inv, acc_o[j][2*r+1] * inv);
        }
    }
}

// ---------------------------------------------------------------------------
// LayerNorm over last dim (768). One block per row, two-pass (matches ref).
// ---------------------------------------------------------------------------
__global__ __launch_bounds__(256) void ln_kernel(
    const float* __restrict__ X, const float* __restrict__ g,
    const float* __restrict__ be, float* __restrict__ Y)
{
    __shared__ float red[256];
    const int row = blockIdx.x;
    const int tid = threadIdx.x;
    const float* x = X + (size_t)row * ND;

    float s = 0.0f;
    for (int i = tid; i < ND; i += 256) s += x[i];
    red[tid] = s; __syncthreads();
    for (int off = 128; off > 0; off >>= 1) {
        if (tid < off) red[tid] += red[tid + off];
        __syncthreads();
    }
    float mu = red[0] * (1.0f / ND);
    __syncthreads();

    float vs = 0.0f;
    for (int i = tid; i < ND; i += 256) { float d = x[i] - mu; vs = fmaf(d, d, vs); }
    red[tid] = vs; __syncthreads();
    for (int off = 128; off > 0; off >>= 1) {
        if (tid < off) red[tid] += red[tid + off];
        __syncthreads();
    }
    float rstd = rsqrtf(red[0] * (1.0f / ND) + 1e-5f);

    for (int i = tid; i < ND; i += 256)
        Y[(size_t)row * ND + i] = (x[i] - mu) * rstd * g[i] + be[i];
}

// ---------------------------------------------------------------------------
extern "C" void kernel_launch(void* const* d_in, const int* in_sizes, int n_in,
                              void* d_out, int out_size)
{
    const float* x   = (const float*)d_in[0];
    // d_in[1] = mask, d_in[2] = alibi_bias  (computed analytically, not read)
    const float* wq  = (const float*)d_in[3];
    const float* bq  = (const float*)d_in[4];
    const float* wk  = (const float*)d_in[5];
    const float* bk  = (const float*)d_in[6];
    const float* wv  = (const float*)d_in[7];
    const float* bv  = (const float*)d_in[8];
    const float* wo  = (const float*)d_in[9];
    const float* bo  = (const float*)d_in[10];
    const float* w1  = (const float*)d_in[11];
    const float* b1  = (const float*)d_in[12];
    const float* w2  = (const float*)d_in[13];
    const float* b2  = (const float*)d_in[14];
    const float* g1  = (const float*)d_in[15];
    const float* be1 = (const float*)d_in[16];
    const float* g2  = (const float*)d_in[17];
    const float* be2 = (const float*)d_in[18];
    float* out = (float*)d_out;

    float *q_p, *k_p, *v_p, *attn_p, *tmp_p, *x1_p, *ff_p;
    cudaGetSymbolAddress((void**)&q_p,   g_q);
    cudaGetSymbolAddress((void**)&k_p,   g_k);
    cudaGetSymbolAddress((void**)&v_p,   g_v);
    cudaGetSymbolAddress((void**)&attn_p,g_attn);
    cudaGetSymbolAddress((void**)&tmp_p, g_tmp);
    cudaGetSymbolAddress((void**)&x1_p,  g_x1);
    cudaGetSymbolAddress((void**)&ff_p,  g_ff);

    cudaFuncSetAttribute(attn_tc, cudaFuncAttributeMaxDynamicSharedMemorySize, ATT_SMEM);
    cudaFuncSetAttribute(gemm_tc, cudaFuncAttributeMaxDynamicSharedMemorySize, GEMM_SMEM);

    // QKV projections -> (B,H,S,HD)
    gemm_tc<<<dim3(ND/128,  NM/128), 256, GEMM_SMEM>>>(x, wq, bq, nullptr, q_p, NM, ND, ND, 0, 1);
    gemm_tc<<<dim3(ND/128,  NM/128), 256, GEMM_SMEM>>>(x, wk, bk, nullptr, k_p, NM, ND, ND, 0, 1);
    gemm_tc<<<dim3(ND/128,  NM/128), 256, GEMM_SMEM>>>(x, wv, bv, nullptr, v_p, NM, ND, ND, 0, 1);

    // attention -> (B,S,D)
    attn_tc<<<dim3(NS/64, NB*NH), 128, ATT_SMEM>>>(q_p, k_p, v_p, attn_p);

    // O projection + residual, then LN1
    gemm_tc<<<dim3(ND/128,  NM/128), 256, GEMM_SMEM>>>(attn_p, wo, bo, x, tmp_p, NM, ND, ND, 0, 0);
    ln_kernel<<<NM, 256>>>(tmp_p, g1, be1, x1_p);

    // FFN
    gemm_tc<<<dim3(NFF/128, NM/128), 256, GEMM_SMEM>>>(x1_p, w1, b1, nullptr, ff_p, NM, NFF, ND, 1, 0);
    gemm_tc<<<dim3(ND/128,  NM/128), 256, GEMM_SMEM>>>(ff_p, w2, b2, x1_p, tmp_p, NM, ND, NFF, 0, 0);
    ln_kernel<<<NM, 256>>>(tmp_p, g2, be2, out);
}